// round 1
// baseline (speedup 1.0000x reference)
#include <cuda_runtime.h>
#include <cuda_bf16.h>

// LatentMap: for each of N_Q queries, gather K=4 neighbor embeddings (EMB=32)
// and blend with inverse-distance-normalized weights, scaled by harmonics.
//
// Layout: one warp per query, one lane per feature (EMB == 32 == warpSize).
// Scalar per-query work (position, neighbor indices, distances, weights) is
// replicated across lanes (uniform addresses -> L1 broadcast). Embedding
// gathers and output stores are perfectly coalesced 128B lines.

#define IMG 1024
#define EMB 32

__global__ void __launch_bounds__(256) latent_map_kernel(
    const float2* __restrict__ position,      // [N_Q] (x, y)
    const float2* __restrict__ positions,     // [N_PTS] (x, y)
    const int4*   __restrict__ neighbor_map,  // [IMG*IMG] 4 indices
    const float*  __restrict__ embeddings,    // [N_PTS, EMB]
    const float*  __restrict__ harmonics,     // [EMB]
    float*        __restrict__ out,           // [N_Q, EMB]
    int n_q)
{
    const int gtid = blockIdx.x * blockDim.x + threadIdx.x;
    const int q = gtid >> 5;        // warp index == query index
    const int f = gtid & 31;        // lane == feature
    if (q >= n_q) return;

    // Per-query scalar loads (uniform within warp -> broadcast)
    const float2 p = position[q];
    const int ix = (int)floorf(p.x);
    const int iy = (int)floorf(p.y);
    const int4 nb = neighbor_map[ix * IMG + iy];

    // Issue all gathers early (MLP)
    const float2 p0 = positions[nb.x];
    const float2 p1 = positions[nb.y];
    const float2 p2 = positions[nb.z];
    const float2 p3 = positions[nb.w];
    const float e0 = embeddings[(long)nb.x * EMB + f];
    const float e1 = embeddings[(long)nb.y * EMB + f];
    const float e2 = embeddings[(long)nb.z * EMB + f];
    const float e3 = embeddings[(long)nb.w * EMB + f];
    const float h  = harmonics[f];

    const float fx = (float)ix, fy = (float)iy;
    float dx, dy;
    dx = p0.x - fx; dy = p0.y - fy;
    const float d0 = sqrtf(dx * dx + dy * dy);
    dx = p1.x - fx; dy = p1.y - fy;
    const float d1 = sqrtf(dx * dx + dy * dy);
    dx = p2.x - fx; dy = p2.y - fy;
    const float d2 = sqrtf(dx * dx + dy * dy);
    dx = p3.x - fx; dy = p3.y - fy;
    const float d3 = sqrtf(dx * dx + dy * dy);

    const float s  = d0 + d1 + d2 + d3;
    const float rs = 1.0f / (s + 1e-8f);
    const float w0 = 1.0f - d0 * rs;
    const float w1 = 1.0f - d1 * rs;
    const float w2 = 1.0f - d2 * rs;
    const float w3 = 1.0f - d3 * rs;

    const float acc = w0 * e0 + w1 * e1 + w2 * e2 + w3 * e3;
    out[(long)q * EMB + f] = acc * h;
}

extern "C" void kernel_launch(void* const* d_in, const int* in_sizes, int n_in,
                              void* d_out, int out_size)
{
    const float2* position     = (const float2*)d_in[0];  // N_Q*2 f32
    const float2* positions    = (const float2*)d_in[1];  // N_PTS*2 f32
    const int4*   neighbor_map = (const int4*)d_in[2];    // IMG*IMG*4 i32
    const float*  embeddings   = (const float*)d_in[3];   // N_PTS*EMB f32
    const float*  harmonics    = (const float*)d_in[4];   // EMB f32
    float*        out          = (float*)d_out;

    const int n_q = in_sizes[0] / 2;
    const long total_threads = (long)n_q * 32;
    const int block = 256;
    const int grid = (int)((total_threads + block - 1) / block);
    latent_map_kernel<<<grid, block>>>(position, positions, neighbor_map,
                                       embeddings, harmonics, out, n_q);
}

// round 3
// speedup vs baseline: 2.4941x; 2.4941x over previous
#include <cuda_runtime.h>
#include <cuda_bf16.h>

// LatentMap, warp-cooperative two-phase scheme.
//
// Phase 1: lane l of each warp computes the per-query scalars (neighbor
//          indices + normalized inverse-distance weights) for query
//          qbase + l, once (no replication), and parks them in smem.
// Phase 2: the warp sweeps its 32 queries; each lane handles one feature
//          (EMB == 32 == warpSize). Per query: 2 broadcast LDS.128,
//          4 coalesced 128B embedding gathers, 5 FFMA, 1 coalesced store.

#define IMG 1024
#define EMB 32
#define WARPS_PER_BLOCK 8
#define QUERIES_PER_WARP 32

__global__ void __launch_bounds__(WARPS_PER_BLOCK * 32) latent_map_kernel(
    const float2* __restrict__ position,      // [N_Q]
    const float2* __restrict__ positions,     // [N_PTS]
    const int4*   __restrict__ neighbor_map,  // [IMG*IMG]
    const float*  __restrict__ embeddings,    // [N_PTS, EMB]
    const float*  __restrict__ harmonics,     // [EMB]
    float*        __restrict__ out,           // [N_Q, EMB]
    int n_q)
{
    __shared__ int4   s_nb[WARPS_PER_BLOCK][QUERIES_PER_WARP];
    __shared__ float4 s_w [WARPS_PER_BLOCK][QUERIES_PER_WARP];

    const int warp = threadIdx.x >> 5;
    const int lane = threadIdx.x & 31;
    const int qbase = (blockIdx.x * WARPS_PER_BLOCK + warp) * QUERIES_PER_WARP;

    // ---- Phase 1: one query per lane, scalar work done exactly once ----
    {
        const int q = qbase + lane;
        if (q < n_q) {
            const float2 p = position[q];
            const int ix = (int)floorf(p.x);
            const int iy = (int)floorf(p.y);
            const int4 nb = neighbor_map[ix * IMG + iy];

            const float2 p0 = positions[nb.x];
            const float2 p1 = positions[nb.y];
            const float2 p2 = positions[nb.z];
            const float2 p3 = positions[nb.w];

            const float fx = (float)ix, fy = (float)iy;
            float dx, dy;
            dx = p0.x - fx; dy = p0.y - fy;
            const float d0 = sqrtf(dx * dx + dy * dy);
            dx = p1.x - fx; dy = p1.y - fy;
            const float d1 = sqrtf(dx * dx + dy * dy);
            dx = p2.x - fx; dy = p2.y - fy;
            const float d2 = sqrtf(dx * dx + dy * dy);
            dx = p3.x - fx; dy = p3.y - fy;
            const float d3 = sqrtf(dx * dx + dy * dy);

            const float rs = 1.0f / (d0 + d1 + d2 + d3 + 1e-8f);
            float4 w;
            w.x = 1.0f - d0 * rs;
            w.y = 1.0f - d1 * rs;
            w.z = 1.0f - d2 * rs;
            w.w = 1.0f - d3 * rs;

            s_nb[warp][lane] = nb;
            s_w [warp][lane] = w;
        }
    }
    __syncwarp();

    // ---- Phase 2: sweep 32 queries, lane == feature ----
    const float h = __ldg(&harmonics[lane]);
    const int n_iter = min(QUERIES_PER_WARP, n_q - qbase);

    #pragma unroll 4
    for (int i = 0; i < n_iter; ++i) {
        const int4   nb = s_nb[warp][i];   // broadcast LDS.128
        const float4 w  = s_w [warp][i];   // broadcast LDS.128

        const float e0 = __ldg(&embeddings[(long)nb.x * EMB + lane]);
        const float e1 = __ldg(&embeddings[(long)nb.y * EMB + lane]);
        const float e2 = __ldg(&embeddings[(long)nb.z * EMB + lane]);
        const float e3 = __ldg(&embeddings[(long)nb.w * EMB + lane]);

        const float acc = w.x * e0 + w.y * e1 + w.z * e2 + w.w * e3;
        out[(long)(qbase + i) * EMB + lane] = acc * h;
    }
}

extern "C" void kernel_launch(void* const* d_in, const int* in_sizes, int n_in,
                              void* d_out, int out_size)
{
    const float2* position     = (const float2*)d_in[0];
    const float2* positions    = (const float2*)d_in[1];
    const int4*   neighbor_map = (const int4*)d_in[2];
    const float*  embeddings   = (const float*)d_in[3];
    const float*  harmonics    = (const float*)d_in[4];
    float*        out          = (float*)d_out;

    const int n_q = in_sizes[0] / 2;
    const int queries_per_block = WARPS_PER_BLOCK * QUERIES_PER_WARP;
    const int grid = (n_q + queries_per_block - 1) / queries_per_block;
    latent_map_kernel<<<grid, WARPS_PER_BLOCK * 32>>>(
        position, positions, neighbor_map, embeddings, harmonics, out, n_q);
}

// round 4
// speedup vs baseline: 2.8838x; 1.1563x over previous
#include <cuda_runtime.h>
#include <cuda_bf16.h>

// LatentMap, warp-cooperative two-phase scheme, 4-queries-per-iteration blend.
//
// Phase 1: lane l computes per-query scalars (neighbor indices + normalized
//          inverse-distance weights) for query qbase + l, once, -> smem.
// Phase 2: the warp sweeps its 32 queries 4 at a time. Lane l serves query
//          sub = l>>3 and feature quad (l&7)*4 via float4:
//          2 conflict-free LDS.128, 4 LDG.128 gathers (4 lines each),
//          1 STG.128 spanning 512B contiguous output, ~20 FFMA.

#define IMG 1024
#define EMB 32
#define WARPS_PER_BLOCK 8
#define QUERIES_PER_WARP 32

__global__ void __launch_bounds__(WARPS_PER_BLOCK * 32) latent_map_kernel(
    const float2* __restrict__ position,      // [N_Q]
    const float2* __restrict__ positions,     // [N_PTS]
    const int4*   __restrict__ neighbor_map,  // [IMG*IMG]
    const float*  __restrict__ embeddings,    // [N_PTS, EMB]
    const float*  __restrict__ harmonics,     // [EMB]
    float*        __restrict__ out,           // [N_Q, EMB]
    int n_q)
{
    __shared__ int4   s_nb[WARPS_PER_BLOCK][QUERIES_PER_WARP];
    __shared__ float4 s_w [WARPS_PER_BLOCK][QUERIES_PER_WARP];

    const int warp = threadIdx.x >> 5;
    const int lane = threadIdx.x & 31;
    const int qbase = (blockIdx.x * WARPS_PER_BLOCK + warp) * QUERIES_PER_WARP;

    // ---- Phase 1: one query per lane, scalar work done exactly once ----
    {
        const int q = qbase + lane;
        if (q < n_q) {
            const float2 p = position[q];
            const int ix = (int)floorf(p.x);
            const int iy = (int)floorf(p.y);
            const int4 nb = neighbor_map[ix * IMG + iy];

            const float2 p0 = positions[nb.x];
            const float2 p1 = positions[nb.y];
            const float2 p2 = positions[nb.z];
            const float2 p3 = positions[nb.w];

            const float fx = (float)ix, fy = (float)iy;
            float dx, dy;
            dx = p0.x - fx; dy = p0.y - fy;
            const float d0 = sqrtf(dx * dx + dy * dy);
            dx = p1.x - fx; dy = p1.y - fy;
            const float d1 = sqrtf(dx * dx + dy * dy);
            dx = p2.x - fx; dy = p2.y - fy;
            const float d2 = sqrtf(dx * dx + dy * dy);
            dx = p3.x - fx; dy = p3.y - fy;
            const float d3 = sqrtf(dx * dx + dy * dy);

            const float rs = 1.0f / (d0 + d1 + d2 + d3 + 1e-8f);
            float4 w;
            w.x = 1.0f - d0 * rs;
            w.y = 1.0f - d1 * rs;
            w.z = 1.0f - d2 * rs;
            w.w = 1.0f - d3 * rs;

            s_nb[warp][lane] = nb;
            s_w [warp][lane] = w;
        }
    }
    __syncwarp();

    // ---- Phase 2: 4 queries per iteration; lane -> (query sub, feature quad)
    const int sub = lane >> 3;        // 0..3 : which of the 4 queries
    const int fq  = (lane & 7) * 4;   // feature quad base: 0,4,...,28

    const float4 h4 = *(const float4*)&harmonics[fq];

    #pragma unroll
    for (int i = 0; i < QUERIES_PER_WARP; i += 4) {
        const int q = qbase + i + sub;
        if (q < n_q) {
            const int4   nb = s_nb[warp][i + sub];  // LDS.128, 4 distinct addrs
            const float4 w  = s_w [warp][i + sub];  // LDS.128

            const float4 e0 = *(const float4*)&embeddings[(long)nb.x * EMB + fq];
            const float4 e1 = *(const float4*)&embeddings[(long)nb.y * EMB + fq];
            const float4 e2 = *(const float4*)&embeddings[(long)nb.z * EMB + fq];
            const float4 e3 = *(const float4*)&embeddings[(long)nb.w * EMB + fq];

            float4 acc;
            acc.x = w.x * e0.x + w.y * e1.x + w.z * e2.x + w.w * e3.x;
            acc.y = w.x * e0.y + w.y * e1.y + w.z * e2.y + w.w * e3.y;
            acc.z = w.x * e0.z + w.y * e1.z + w.z * e2.z + w.w * e3.z;
            acc.w = w.x * e0.w + w.y * e1.w + w.z * e2.w + w.w * e3.w;

            acc.x *= h4.x; acc.y *= h4.y; acc.z *= h4.z; acc.w *= h4.w;

            *(float4*)&out[(long)q * EMB + fq] = acc;
        }
    }
}

extern "C" void kernel_launch(void* const* d_in, const int* in_sizes, int n_in,
                              void* d_out, int out_size)
{
    const float2* position     = (const float2*)d_in[0];
    const float2* positions    = (const float2*)d_in[1];
    const int4*   neighbor_map = (const int4*)d_in[2];
    const float*  embeddings   = (const float*)d_in[3];
    const float*  harmonics    = (const float*)d_in[4];
    float*        out          = (float*)d_out;

    const int n_q = in_sizes[0] / 2;
    const int queries_per_block = WARPS_PER_BLOCK * QUERIES_PER_WARP;
    const int grid = (n_q + queries_per_block - 1) / queries_per_block;
    latent_map_kernel<<<grid, WARPS_PER_BLOCK * 32>>>(
        position, positions, neighbor_map, embeddings, harmonics, out, n_q);
}